// round 3
// baseline (speedup 1.0000x reference)
#include <cuda_runtime.h>

// Problem constants (fixed shapes from reference)
#define NB 16
#define NC 31
#define NHW 65536
#define NPAIR 496          // NC*(NC+1)/2 upper-triangular pairs
#define TILE_K 128

#define S1_CHUNKS 8        // stage-1 subset: 8 chunks x 1024 cols = 8192 columns
#define S1_CHUNK_K 1024
#define S2_CHUNKS 14       // stage-2 remainder: 14 chunks x 4096 = 57344 columns
#define S2_CHUNK_K 4096
#define S2_KBASE 8192

// Scratch (no allocations allowed -> device globals). Partial-sum layout means
// every replay fully overwrites them: no zeroing kernel, no atomics.
__device__ float g_p1[NB * S1_CHUNKS * NPAIR];
__device__ float g_p2[NB * S2_CHUNKS * NPAIR];
__device__ float g_M[NB * NC * NC];
__device__ int   g_flag[NB];   // 1 => SVT is provably identity for batch b

__device__ __forceinline__ int pair_index(int i, int j) {
    // i <= j, upper-triangular linearization
    return i * NC - (i * (i - 1)) / 2 + (j - i);
}

// ---------------------------------------------------------------------------
// Gram partial sums over a column range. grid = (NB, n_chunks), block = 512.
// which: 0 -> g_p1, 1 -> g_p2. gated: skip batch if identity already proven.
// ---------------------------------------------------------------------------
__global__ __launch_bounds__(512)
void gram_kernel(const float* __restrict__ x, int k_base, int chunk_k,
                 int which, int gated) {
    int b = blockIdx.x;
    if (gated && g_flag[b]) return;

    __shared__ float xs[NC][TILE_K + 1];
    int t = threadIdx.x;

    // invert triangular index -> (i, j), i <= j
    int pi = 0, pj = 0;
    if (t < NPAIR) {
        int tt = t, i = 0;
        while (tt >= NC - i) { tt -= (NC - i); i++; }
        pi = i; pj = i + tt;
    }

    const float* xb = x + (size_t)b * NC * NHW;
    int k0 = k_base + blockIdx.y * chunk_k;
    float acc = 0.0f;

    for (int kt = 0; kt < chunk_k; kt += TILE_K) {
        for (int idx = t; idx < NC * TILE_K; idx += blockDim.x) {
            int c = idx >> 7, kk = idx & (TILE_K - 1);
            xs[c][kk] = xb[c * NHW + k0 + kt + kk];
        }
        __syncthreads();
        if (t < NPAIR) {
            #pragma unroll 8
            for (int kk = 0; kk < TILE_K; kk++)
                acc = fmaf(xs[pi][kk], xs[pj][kk], acc);
        }
        __syncthreads();
    }

    if (t < NPAIR) {
        if (which == 0)
            g_p1[(b * S1_CHUNKS + blockIdx.y) * NPAIR + t] = acc;
        else
            g_p2[(b * S2_CHUNKS + blockIdx.y) * NPAIR + t] = acc;
    }
}

// ---------------------------------------------------------------------------
// Gershgorin on the subset Gram: lambda_min(G_full) >= lambda_min(G_subset)
// >= min_i (G_ii - sum_{j!=i} |G_ij|). If that exceeds thr^2, every singular
// value exceeds thr, the SVT mask is all-ones, and SVT(X) == X exactly.
// ---------------------------------------------------------------------------
__global__ void decide_kernel(const float* __restrict__ soft_thr) {
    int b = blockIdx.x;
    int lane = threadIdx.x;   // 32 threads
    float bound = 1e30f;
    if (lane < NC) {
        float diag = 0.0f, offs = 0.0f;
        for (int j = 0; j < NC; j++) {
            int i0 = lane < j ? lane : j;
            int j0 = lane < j ? j : lane;
            int t = pair_index(i0, j0);
            float g = 0.0f;
            #pragma unroll
            for (int cch = 0; cch < S1_CHUNKS; cch++)
                g += g_p1[(b * S1_CHUNKS + cch) * NPAIR + t];
            if (j == lane) diag = g; else offs += fabsf(g);
        }
        bound = diag - offs;
    }
    for (int o = 16; o > 0; o >>= 1)
        bound = fminf(bound, __shfl_xor_sync(0xffffffffu, bound, o));
    if (lane == 0) {
        float thr = soft_thr[0];
        g_flag[b] = (bound > thr * thr) ? 1 : 0;
    }
}

// ---------------------------------------------------------------------------
// Fallback (gated; does not execute when identity was proven): warp Jacobi
// eigendecomposition of the full 31x31 Gram, then M = V diag(mask) V^T.
// ---------------------------------------------------------------------------
__global__ void eig_kernel(const float* __restrict__ soft_thr) {
    int b = blockIdx.x;
    if (g_flag[b]) return;

    __shared__ float A[NC][NC + 2];
    __shared__ float V[NC][NC + 2];
    __shared__ float mask[NC];
    int lane = threadIdx.x;   // 32 threads

    if (lane < NC) {
        for (int i = 0; i < NC; i++) {
            int i0 = i < lane ? i : lane;
            int j0 = i < lane ? lane : i;
            int t = pair_index(i0, j0);
            float g = 0.0f;
            for (int cch = 0; cch < S1_CHUNKS; cch++)
                g += g_p1[(b * S1_CHUNKS + cch) * NPAIR + t];
            for (int cch = 0; cch < S2_CHUNKS; cch++)
                g += g_p2[(b * S2_CHUNKS + cch) * NPAIR + t];
            A[i][lane] = g;
            V[i][lane] = (i == lane) ? 1.0f : 0.0f;
        }
    }
    __syncwarp();

    for (int sweep = 0; sweep < 12; sweep++) {
        for (int p = 0; p < NC - 1; p++) {
            for (int q = p + 1; q < NC; q++) {
                float apq = A[p][q];
                float app = A[p][p], aqq = A[q][q];
                if (fabsf(apq) <= 1e-12f * (fabsf(app) + fabsf(aqq)) + 1e-30f)
                    continue;
                float theta = 0.5f * (aqq - app) / apq;
                float tt = copysignf(1.0f, theta) /
                           (fabsf(theta) + sqrtf(1.0f + theta * theta));
                float c = rsqrtf(1.0f + tt * tt);
                float s = tt * c;
                if (lane < NC) {
                    float Apk = A[p][lane], Aqk = A[q][lane];
                    A[p][lane] = c * Apk - s * Aqk;
                    A[q][lane] = s * Apk + c * Aqk;
                }
                __syncwarp();
                if (lane < NC) {
                    float Akp = A[lane][p], Akq = A[lane][q];
                    A[lane][p] = c * Akp - s * Akq;
                    A[lane][q] = s * Akp + c * Akq;
                    float Vkp = V[lane][p], Vkq = V[lane][q];
                    V[lane][p] = c * Vkp - s * Vkq;
                    V[lane][q] = s * Vkp + c * Vkq;
                }
                __syncwarp();
            }
        }
    }

    if (lane < NC) {
        float lam = A[lane][lane];
        float sv = sqrtf(fmaxf(lam, 0.0f));
        mask[lane] = (sv > soft_thr[0]) ? 1.0f : 0.0f;
    }
    __syncwarp();

    if (lane < NC) {
        for (int r = 0; r < NC; r++) {
            float m = 0.0f;
            for (int i = 0; i < NC; i++)
                m += mask[i] * V[r][i] * V[lane][i];
            g_M[(b * NC + r) * NC + lane] = m;
        }
    }
}

// ---------------------------------------------------------------------------
// Apply: identity -> vectorized streaming copy; otherwise out = M @ x.
// One flat grid over all elements; per-element batch derived from index so
// flagged/unflagged batches share the grid without imbalance.
// ---------------------------------------------------------------------------
#define PER_B4 (NC * NHW / 4)   // float4 elements per batch = 507904

__global__ __launch_bounds__(256)
void apply_kernel(const float* __restrict__ x, float* __restrict__ out) {
    const float4* src = (const float4*)x;
    float4*       dst = (float4*)out;
    int stride = gridDim.x * blockDim.x;
    int total4 = NB * PER_B4;

    for (int i = blockIdx.x * blockDim.x + threadIdx.x; i < total4; i += stride) {
        int b = i / PER_B4;
        if (g_flag[b]) {
            dst[i] = src[i];
        } else {
            // Fallback: out = M @ x for this batch (rare path). Compute the
            // 4 spatial positions covered by this float4 across all rows.
            int r = i - b * PER_B4;           // float4 index within batch
            int c = r / (NHW / 4);            // channel row
            int k4 = r - c * (NHW / 4);       // float4 pos within row
            const float* xb = x + (size_t)b * NC * NHW;
            const float* M  = g_M + b * NC * NC;
            float4 acc = make_float4(0.f, 0.f, 0.f, 0.f);
            for (int j = 0; j < NC; j++) {
                float m = M[c * NC + j];
                const float4 xv = ((const float4*)(xb + (size_t)j * NHW))[k4];
                acc.x = fmaf(m, xv.x, acc.x);
                acc.y = fmaf(m, xv.y, acc.y);
                acc.z = fmaf(m, xv.z, acc.z);
                acc.w = fmaf(m, xv.w, acc.w);
            }
            dst[i] = acc;
        }
    }
}

extern "C" void kernel_launch(void* const* d_in, const int* in_sizes, int n_in,
                              void* d_out, int out_size) {
    // Identify inputs by size for robustness: soft_thr has 1 element,
    // x has NB*NC*NHW elements.
    const float* x   = (const float*)d_in[0];
    const float* thr = (const float*)d_in[1];
    if (n_in >= 2) {
        if (in_sizes[0] == 1) { thr = (const float*)d_in[0]; x = (const float*)d_in[1]; }
        else                  { x  = (const float*)d_in[0]; thr = (const float*)d_in[1]; }
    }
    float* out = (float*)d_out;

    // 1) Gram partial sums over first 8192 columns (subset bound is rigorous:
    //    adding more columns only adds a PSD term).
    gram_kernel<<<dim3(NB, S1_CHUNKS), 512>>>(x, 0, S1_CHUNK_K, 0, 0);
    // 2) Gershgorin decision per batch.
    decide_kernel<<<NB, 32>>>(thr);
    // 3) Fallback path (early-exits when identity proven): remaining columns,
    //    Jacobi eigensolve, projection matrix.
    gram_kernel<<<dim3(NB, S2_CHUNKS), 512>>>(x, S2_KBASE, S2_CHUNK_K, 1, 1);
    eig_kernel<<<NB, 32>>>(thr);
    // 4) Produce output: streaming copy (proven-identity) or M @ x.
    apply_kernel<<<2048, 256>>>(x, out);
}

// round 6
// speedup vs baseline: 1.2476x; 1.2476x over previous
#include <cuda_runtime.h>

// Fixed shapes
#define NB 16
#define NC 31
#define NHW 65536
#define NPAIR 496              // NC*(NC+1)/2
#define TILE_K 128

// K1 layout: gram blocks first, then copy blocks
#define GRAM_CHUNKS 8          // per batch
#define GRAM_BLOCKS (NB * GRAM_CHUNKS)   // 128
#define SUB_CHUNK 512          // columns per gram block -> 4096-col subset
#define COPY_BLOCKS 2048
#define K1_BLOCKS (GRAM_BLOCKS + COPY_BLOCKS)
#define K1_THREADS 256

#define TOTAL4 (NB * NC * NHW / 4)   // float4 elements total = 8126464

// Scratch (device globals; fully overwritten every replay -> deterministic)
__device__ float g_p1[NB * GRAM_CHUNKS * NPAIR];
__device__ int   g_flag[NB];   // 1 => SVT provably identity for batch b

__device__ __forceinline__ int pair_index(int i, int j) {
    return i * NC - (i * (i - 1)) / 2 + (j - i);   // i <= j
}

// ---------------------------------------------------------------------------
// K1: fused streaming copy + subset-Gram partials.
//   blockIdx.x <  GRAM_BLOCKS : Gram over SUB_CHUNK columns of one batch
//   blockIdx.x >= GRAM_BLOCKS : float4 copy with streaming hints
// The copy is unconditionally correct when the Gershgorin proof fires (it
// always does for this data: sigma_min ~ 250 >> thr = 1e-4); the gated
// fallback overwrites it otherwise. Gram runs concurrently with the copy.
// ---------------------------------------------------------------------------
__global__ __launch_bounds__(K1_THREADS)
void copy_gram_kernel(const float* __restrict__ x, float* __restrict__ out) {
    int t = threadIdx.x;

    if (blockIdx.x < GRAM_BLOCKS) {
        // ---- subset Gram partial for (batch, chunk) ----
        int g = blockIdx.x;
        int b = g >> 3;
        int chunk = g & 7;
        int k0 = chunk * SUB_CHUNK;

        __shared__ float xs[NC][TILE_K + 1];

        // two pairs per thread: t and t+256
        int pi0 = 0, pj0 = 0, pi1 = 0, pj1 = 0;
        {
            int tt = t, i = 0;
            while (tt >= NC - i) { tt -= (NC - i); i++; }
            pi0 = i; pj0 = i + tt;
        }
        int t1 = t + K1_THREADS;
        if (t1 < NPAIR) {
            int tt = t1, i = 0;
            while (tt >= NC - i) { tt -= (NC - i); i++; }
            pi1 = i; pj1 = i + tt;
        }

        const float* xb = x + (size_t)b * NC * NHW;
        float acc0 = 0.0f, acc1 = 0.0f;

        for (int kt = 0; kt < SUB_CHUNK; kt += TILE_K) {
            for (int idx = t; idx < NC * TILE_K; idx += K1_THREADS) {
                int c = idx >> 7, kk = idx & (TILE_K - 1);
                xs[c][kk] = xb[c * NHW + k0 + kt + kk];
            }
            __syncthreads();
            #pragma unroll 8
            for (int kk = 0; kk < TILE_K; kk++) {
                acc0 = fmaf(xs[pi0][kk], xs[pj0][kk], acc0);
                acc1 = fmaf(xs[pi1][kk], xs[pj1][kk], acc1);
            }
            __syncthreads();
        }

        g_p1[(b * GRAM_CHUNKS + chunk) * NPAIR + t] = acc0;
        if (t1 < NPAIR)
            g_p1[(b * GRAM_CHUNKS + chunk) * NPAIR + t1] = acc1;
    } else {
        // ---- streaming copy ----
        // TOTAL4 = 15.5 * span. 7 unconditional double-iterations cover
        // spans [0,14); the tail loop covers span 14, span 15 where present,
        // i.e. EVERY i < TOTAL4. (R5 bug: tail was a single pass and left
        // the last half-span unwritten -> rel_err sqrt(1/31).)
        const float4* src = (const float4*)x;
        float4*       dst = (float4*)out;
        const int span = COPY_BLOCKS * K1_THREADS;   // 524288
        int i = (blockIdx.x - GRAM_BLOCKS) * K1_THREADS + t;
        #pragma unroll 1
        for (int it = 0; it < 7; it++) {
            float4 v0 = __ldcs(src + i);
            float4 v1 = __ldcs(src + i + span);
            __stcs(dst + i, v0);
            __stcs(dst + i + span, v1);
            i += 2 * span;
        }
        #pragma unroll 1
        for (; i < TOTAL4; i += span) {
            float4 v = __ldcs(src + i);
            __stcs(dst + i, v);
        }
    }
}

// ---------------------------------------------------------------------------
// K2: Gershgorin on the 4096-column subset Gram.
// lambda_min(G_full) >= lambda_min(G_subset) >= min_i (G_ii - sum_j |G_ij|).
// If that exceeds thr^2, every singular value exceeds thr -> SVT == identity.
// ---------------------------------------------------------------------------
__global__ void decide_kernel(const float* __restrict__ soft_thr) {
    int b = blockIdx.x;
    int lane = threadIdx.x;   // 32
    float bound = 1e30f;
    if (lane < NC) {
        float diag = 0.0f, offs = 0.0f;
        for (int j = 0; j < NC; j++) {
            int i0 = lane < j ? lane : j;
            int j0 = lane < j ? j : lane;
            int tt = pair_index(i0, j0);
            float g = 0.0f;
            #pragma unroll
            for (int cch = 0; cch < GRAM_CHUNKS; cch++)
                g += g_p1[(b * GRAM_CHUNKS + cch) * NPAIR + tt];
            if (j == lane) diag = g; else offs += fabsf(g);
        }
        bound = diag - offs;
    }
    for (int o = 16; o > 0; o >>= 1)
        bound = fminf(bound, __shfl_xor_sync(0xffffffffu, bound, o));
    if (lane == 0) {
        float thr = soft_thr[0];
        g_flag[b] = (bound > thr * thr) ? 1 : 0;
    }
}

// ---------------------------------------------------------------------------
// K3: gated fallback. One block per batch; early-exits when identity proven.
// If taken: full 31x31 Gram over all columns, Jacobi eigendecomposition,
// M = V diag(mask) V^T, then out = M @ x (overwrites the speculative copy).
// Correctness-only path; never executes for in-distribution data.
// ---------------------------------------------------------------------------
__global__ __launch_bounds__(1024)
void fallback_kernel(const float* __restrict__ x, float* __restrict__ out,
                     const float* __restrict__ soft_thr) {
    int b = blockIdx.x;
    if (g_flag[b]) return;

    __shared__ float xs[NC][TILE_K + 1];
    __shared__ float A[NC][NC + 2];
    __shared__ float V[NC][NC + 2];
    __shared__ float M[NC][NC + 1];
    __shared__ float mask[NC];

    int t = threadIdx.x;
    const float* xb = x + (size_t)b * NC * NHW;

    // pair mapping for t < NPAIR
    int pi = 0, pj = 0;
    if (t < NPAIR) {
        int tt = t, i = 0;
        while (tt >= NC - i) { tt -= (NC - i); i++; }
        pi = i; pj = i + tt;
    }

    // full Gram
    float acc = 0.0f;
    for (int k0 = 0; k0 < NHW; k0 += TILE_K) {
        for (int idx = t; idx < NC * TILE_K; idx += blockDim.x) {
            int c = idx >> 7, kk = idx & (TILE_K - 1);
            xs[c][kk] = xb[c * NHW + k0 + kk];
        }
        __syncthreads();
        if (t < NPAIR) {
            #pragma unroll 8
            for (int kk = 0; kk < TILE_K; kk++)
                acc = fmaf(xs[pi][kk], xs[pj][kk], acc);
        }
        __syncthreads();
    }
    if (t < NPAIR) {
        A[pi][pj] = acc;
        A[pj][pi] = acc;
    }
    if (t < NC * NC) {
        int i = t / NC, j = t % NC;
        V[i][j] = (i == j) ? 1.0f : 0.0f;
    }
    __syncthreads();

    // Jacobi (warp 0 only)
    if (t < 32) {
        int lane = t;
        for (int sweep = 0; sweep < 12; sweep++) {
            for (int p = 0; p < NC - 1; p++) {
                for (int q = p + 1; q < NC; q++) {
                    float apq = A[p][q];
                    float app = A[p][p], aqq = A[q][q];
                    if (fabsf(apq) <= 1e-12f * (fabsf(app) + fabsf(aqq)) + 1e-30f)
                        continue;
                    float theta = 0.5f * (aqq - app) / apq;
                    float tt2 = copysignf(1.0f, theta) /
                                (fabsf(theta) + sqrtf(1.0f + theta * theta));
                    float c = rsqrtf(1.0f + tt2 * tt2);
                    float s = tt2 * c;
                    if (lane < NC) {
                        float Apk = A[p][lane], Aqk = A[q][lane];
                        A[p][lane] = c * Apk - s * Aqk;
                        A[q][lane] = s * Apk + c * Aqk;
                    }
                    __syncwarp();
                    if (lane < NC) {
                        float Akp = A[lane][p], Akq = A[lane][q];
                        A[lane][p] = c * Akp - s * Akq;
                        A[lane][q] = s * Akp + c * Akq;
                        float Vkp = V[lane][p], Vkq = V[lane][q];
                        V[lane][p] = c * Vkp - s * Vkq;
                        V[lane][q] = s * Vkp + c * Vkq;
                    }
                    __syncwarp();
                }
            }
        }
        if (lane < NC) {
            float sv = sqrtf(fmaxf(A[lane][lane], 0.0f));
            mask[lane] = (sv > soft_thr[0]) ? 1.0f : 0.0f;
        }
        __syncwarp();
        if (lane < NC) {
            for (int r = 0; r < NC; r++) {
                float m = 0.0f;
                for (int i = 0; i < NC; i++)
                    m += mask[i] * V[r][i] * V[lane][i];
                M[r][lane] = m;
            }
        }
    }
    __syncthreads();

    // out = M @ x for this batch
    float* ob = out + (size_t)b * NC * NHW;
    for (int k = t; k < NHW; k += blockDim.x) {
        float xv[NC];
        #pragma unroll
        for (int j = 0; j < NC; j++) xv[j] = xb[(size_t)j * NHW + k];
        #pragma unroll 1
        for (int c = 0; c < NC; c++) {
            float a = 0.0f;
            #pragma unroll
            for (int j = 0; j < NC; j++) a = fmaf(M[c][j], xv[j], a);
            ob[(size_t)c * NHW + k] = a;
        }
    }
}

extern "C" void kernel_launch(void* const* d_in, const int* in_sizes, int n_in,
                              void* d_out, int out_size) {
    // Identify inputs by size (soft_thr has 1 element)
    const float* x   = (const float*)d_in[0];
    const float* thr = (const float*)d_in[1];
    if (n_in >= 2) {
        if (in_sizes[0] == 1) { thr = (const float*)d_in[0]; x = (const float*)d_in[1]; }
        else                  { x  = (const float*)d_in[0]; thr = (const float*)d_in[1]; }
    }
    float* out = (float*)d_out;

    // K1: speculative copy (valid when SVT==identity) + subset-Gram partials
    copy_gram_kernel<<<K1_BLOCKS, K1_THREADS>>>(x, out);
    // K2: Gershgorin decision per batch
    decide_kernel<<<NB, 32>>>(thr);
    // K3: gated fallback — overwrites copy only if identity not proven
    fallback_kernel<<<NB, 1024>>>(x, out, thr);
}

// round 8
// speedup vs baseline: 1.3244x; 1.0616x over previous
#include <cuda_runtime.h>

// Fixed shapes
#define NB 16
#define NC 31
#define NHW 65536
#define NPAIR 496              // NC*(NC+1)/2
#define TILE_K 128

// K1 layout: gram blocks first, then copy blocks
#define GRAM_CHUNKS 8          // per batch
#define GRAM_BLOCKS (NB * GRAM_CHUNKS)   // 128
#define SUB_CHUNK 512          // columns per gram block -> 4096-col subset
#define COPY_BLOCKS 2048
#define K1_BLOCKS (GRAM_BLOCKS + COPY_BLOCKS)
#define K1_THREADS 256

#define TOTAL4 (NB * NC * NHW / 4)   // float4 elements total = 8126464

// Scratch (device globals; fully overwritten / reset every replay)
__device__ float g_p1[NB * GRAM_CHUNKS * NPAIR];
__device__ int   g_cnt[NB];    // arrival ticket per batch (reset by last block)
__device__ int   g_flag[NB];   // 1 => SVT provably identity for batch b

__device__ __forceinline__ int pair_index(int i, int j) {
    return i * NC - (i * (i - 1)) / 2 + (j - i);   // i <= j
}

// ---------------------------------------------------------------------------
// K1: fused streaming copy + subset-Gram partials + inline Gershgorin decide.
//   blockIdx.x <  GRAM_BLOCKS : Gram over SUB_CHUNK columns of one batch;
//                               the LAST arriving block of each batch also
//                               computes the Gershgorin bound and g_flag[b].
//   blockIdx.x >= GRAM_BLOCKS : float4 streaming copy (identical to the
//                               72.3us R6 code path).
// The copy is unconditionally correct when the Gershgorin proof fires
// (sigma_min ~ 250 >> thr = 1e-4 for this data); the gated fallback
// overwrites it otherwise.
// ---------------------------------------------------------------------------
__global__ __launch_bounds__(K1_THREADS)
void copy_gram_kernel(const float* __restrict__ x, float* __restrict__ out,
                      const float* __restrict__ soft_thr) {
    int t = threadIdx.x;

    if (blockIdx.x < GRAM_BLOCKS) {
        // ---- subset Gram partial for (batch, chunk) ----
        int g = blockIdx.x;
        int b = g >> 3;
        int chunk = g & 7;
        int k0 = chunk * SUB_CHUNK;

        __shared__ float xs[NC][TILE_K + 1];
        __shared__ int s_ticket;

        // two pairs per thread: t and t+256
        int pi0 = 0, pj0 = 0, pi1 = 0, pj1 = 0;
        {
            int tt = t, i = 0;
            while (tt >= NC - i) { tt -= (NC - i); i++; }
            pi0 = i; pj0 = i + tt;
        }
        int t1 = t + K1_THREADS;
        if (t1 < NPAIR) {
            int tt = t1, i = 0;
            while (tt >= NC - i) { tt -= (NC - i); i++; }
            pi1 = i; pj1 = i + tt;
        }

        const float* xb = x + (size_t)b * NC * NHW;
        float acc0 = 0.0f, acc1 = 0.0f;

        for (int kt = 0; kt < SUB_CHUNK; kt += TILE_K) {
            for (int idx = t; idx < NC * TILE_K; idx += K1_THREADS) {
                int c = idx >> 7, kk = idx & (TILE_K - 1);
                xs[c][kk] = xb[c * NHW + k0 + kt + kk];
            }
            __syncthreads();
            #pragma unroll 8
            for (int kk = 0; kk < TILE_K; kk++) {
                acc0 = fmaf(xs[pi0][kk], xs[pj0][kk], acc0);
                acc1 = fmaf(xs[pi1][kk], xs[pj1][kk], acc1);
            }
            __syncthreads();
        }

        g_p1[(b * GRAM_CHUNKS + chunk) * NPAIR + t] = acc0;
        if (t1 < NPAIR)
            g_p1[(b * GRAM_CHUNKS + chunk) * NPAIR + t1] = acc1;

        // ---- arrival ticket: last block of this batch runs the decide ----
        __threadfence();              // publish partials before ticket
        __syncthreads();              // all stores issued before lane0 tickets
        if (t == 0)
            s_ticket = atomicAdd(&g_cnt[b], 1);
        __syncthreads();
        if (s_ticket == GRAM_CHUNKS - 1) {
            __threadfence();          // acquire: see other blocks' partials
            if (t < 32) {
                int lane = t;
                float bound = 1e30f;
                if (lane < NC) {
                    float diag = 0.0f, offs = 0.0f;
                    for (int j = 0; j < NC; j++) {
                        int i0 = lane < j ? lane : j;
                        int j0 = lane < j ? j : lane;
                        int tt = pair_index(i0, j0);
                        float gg = 0.0f;
                        #pragma unroll
                        for (int cch = 0; cch < GRAM_CHUNKS; cch++)
                            gg += g_p1[(b * GRAM_CHUNKS + cch) * NPAIR + tt];
                        if (j == lane) diag = gg; else offs += fabsf(gg);
                    }
                    bound = diag - offs;
                }
                for (int o = 16; o > 0; o >>= 1)
                    bound = fminf(bound, __shfl_xor_sync(0xffffffffu, bound, o));
                if (lane == 0) {
                    float thr = soft_thr[0];
                    g_flag[b] = (bound > thr * thr) ? 1 : 0;
                    g_cnt[b] = 0;     // reset for next graph replay
                    __threadfence();
                }
            }
        }
    } else {
        // ---- streaming copy (identical to the 72.3us version) ----
        // TOTAL4 = 15.5 * span. 7 unconditional double-iterations cover
        // spans [0,14); the tail loop covers everything else.
        const float4* src = (const float4*)x;
        float4*       dst = (float4*)out;
        const int span = COPY_BLOCKS * K1_THREADS;   // 524288
        int i = (blockIdx.x - GRAM_BLOCKS) * K1_THREADS + t;
        #pragma unroll 1
        for (int it = 0; it < 7; it++) {
            float4 v0 = __ldcs(src + i);
            float4 v1 = __ldcs(src + i + span);
            __stcs(dst + i, v0);
            __stcs(dst + i + span, v1);
            i += 2 * span;
        }
        #pragma unroll 1
        for (; i < TOTAL4; i += span) {
            float4 v = __ldcs(src + i);
            __stcs(dst + i, v);
        }
    }
}

// ---------------------------------------------------------------------------
// K2: gated fallback. One block per batch; early-exits when identity proven.
// If taken: full 31x31 Gram over all columns, Jacobi eigendecomposition,
// M = V diag(mask) V^T, then out = M @ x (overwrites the speculative copy).
// Correctness-only path; never executes for in-distribution data.
// ---------------------------------------------------------------------------
__global__ __launch_bounds__(1024)
void fallback_kernel(const float* __restrict__ x, float* __restrict__ out,
                     const float* __restrict__ soft_thr) {
    int b = blockIdx.x;
    if (g_flag[b]) return;

    __shared__ float xs[NC][TILE_K + 1];
    __shared__ float A[NC][NC + 2];
    __shared__ float V[NC][NC + 2];
    __shared__ float M[NC][NC + 1];
    __shared__ float mask[NC];

    int t = threadIdx.x;
    const float* xb = x + (size_t)b * NC * NHW;

    int pi = 0, pj = 0;
    if (t < NPAIR) {
        int tt = t, i = 0;
        while (tt >= NC - i) { tt -= (NC - i); i++; }
        pi = i; pj = i + tt;
    }

    // full Gram
    float acc = 0.0f;
    for (int k0 = 0; k0 < NHW; k0 += TILE_K) {
        for (int idx = t; idx < NC * TILE_K; idx += blockDim.x) {
            int c = idx >> 7, kk = idx & (TILE_K - 1);
            xs[c][kk] = xb[c * NHW + k0 + kk];
        }
        __syncthreads();
        if (t < NPAIR) {
            #pragma unroll 8
            for (int kk = 0; kk < TILE_K; kk++)
                acc = fmaf(xs[pi][kk], xs[pj][kk], acc);
        }
        __syncthreads();
    }
    if (t < NPAIR) {
        A[pi][pj] = acc;
        A[pj][pi] = acc;
    }
    if (t < NC * NC) {
        int i = t / NC, j = t % NC;
        V[i][j] = (i == j) ? 1.0f : 0.0f;
    }
    __syncthreads();

    // Jacobi (warp 0 only)
    if (t < 32) {
        int lane = t;
        for (int sweep = 0; sweep < 12; sweep++) {
            for (int p = 0; p < NC - 1; p++) {
                for (int q = p + 1; q < NC; q++) {
                    float apq = A[p][q];
                    float app = A[p][p], aqq = A[q][q];
                    if (fabsf(apq) <= 1e-12f * (fabsf(app) + fabsf(aqq)) + 1e-30f)
                        continue;
                    float theta = 0.5f * (aqq - app) / apq;
                    float tt2 = copysignf(1.0f, theta) /
                                (fabsf(theta) + sqrtf(1.0f + theta * theta));
                    float c = rsqrtf(1.0f + tt2 * tt2);
                    float s = tt2 * c;
                    if (lane < NC) {
                        float Apk = A[p][lane], Aqk = A[q][lane];
                        A[p][lane] = c * Apk - s * Aqk;
                        A[q][lane] = s * Apk + c * Aqk;
                    }
                    __syncwarp();
                    if (lane < NC) {
                        float Akp = A[lane][p], Akq = A[lane][q];
                        A[lane][p] = c * Akp - s * Akq;
                        A[lane][q] = s * Akp + c * Akq;
                        float Vkp = V[lane][p], Vkq = V[lane][q];
                        V[lane][p] = c * Vkp - s * Vkq;
                        V[lane][q] = s * Vkp + c * Vkq;
                    }
                    __syncwarp();
                }
            }
        }
        if (lane < NC) {
            float sv = sqrtf(fmaxf(A[lane][lane], 0.0f));
            mask[lane] = (sv > soft_thr[0]) ? 1.0f : 0.0f;
        }
        __syncwarp();
        if (lane < NC) {
            for (int r = 0; r < NC; r++) {
                float m = 0.0f;
                for (int i = 0; i < NC; i++)
                    m += mask[i] * V[r][i] * V[lane][i];
                M[r][lane] = m;
            }
        }
    }
    __syncthreads();

    // out = M @ x for this batch
    float* ob = out + (size_t)b * NC * NHW;
    for (int k = t; k < NHW; k += blockDim.x) {
        float xv[NC];
        #pragma unroll
        for (int j = 0; j < NC; j++) xv[j] = xb[(size_t)j * NHW + k];
        #pragma unroll 1
        for (int c = 0; c < NC; c++) {
            float a = 0.0f;
            #pragma unroll
            for (int j = 0; j < NC; j++) a = fmaf(M[c][j], xv[j], a);
            ob[(size_t)c * NHW + k] = a;
        }
    }
}

extern "C" void kernel_launch(void* const* d_in, const int* in_sizes, int n_in,
                              void* d_out, int out_size) {
    // Identify inputs by size (soft_thr has 1 element)
    const float* x   = (const float*)d_in[0];
    const float* thr = (const float*)d_in[1];
    if (n_in >= 2) {
        if (in_sizes[0] == 1) { thr = (const float*)d_in[0]; x = (const float*)d_in[1]; }
        else                  { x  = (const float*)d_in[0]; thr = (const float*)d_in[1]; }
    }
    float* out = (float*)d_out;

    // K1: speculative copy + subset-Gram + inline Gershgorin decide
    copy_gram_kernel<<<K1_BLOCKS, K1_THREADS>>>(x, out, thr);
    // K2: gated fallback — overwrites copy only if identity not proven
    fallback_kernel<<<NB, 1024>>>(x, out, thr);
}

// round 9
// speedup vs baseline: 1.6283x; 1.2295x over previous
#include <cuda_runtime.h>

// Fixed shapes
#define NB 16
#define NC 31
#define NHW 65536
#define NPAIR 496              // NC*(NC+1)/2
#define TILE_K 128

// K1 layout: gram blocks, copy blocks, then per-batch fallback/spin blocks
#define GRAM_CHUNKS 8          // per batch
#define GRAM_BLOCKS (NB * GRAM_CHUNKS)   // 128
#define SUB_CHUNK 512          // columns per gram block -> 4096-col subset
#define COPY_BLOCKS 2048
#define FB_BASE (GRAM_BLOCKS + COPY_BLOCKS)   // 2176
#define K1_BLOCKS (FB_BASE + NB)              // 2192
#define K1_THREADS 256

#define TOTAL4 (NB * NC * NHW / 4)   // float4 elements total = 8126464

// Scratch (device globals; reset by their consumers every replay)
__device__ float g_p1[NB * GRAM_CHUNKS * NPAIR];
__device__ int   g_cnt[NB];             // arrival ticket (reset by decide)
__device__ int   g_flag[NB];            // 1 => SVT provably identity
__device__ volatile int g_done[NB];     // decide published (reset by spin blk)

__device__ __forceinline__ int pair_index(int i, int j) {
    return i * NC - (i * (i - 1)) / 2 + (j - i);   // i <= j
}

// ---------------------------------------------------------------------------
// Single fused kernel:
//  blocks [0,128)        : subset-Gram partials; last arrival per batch does
//                          the Gershgorin decide, publishes g_flag + g_done.
//  blocks [128,2176)     : float4 streaming copy (identical to 68us path).
//  blocks [2176,2192)    : one per batch — spin until g_done[b], then exit if
//                          identity proven, else full SVT fallback in-place.
// The copy is unconditionally correct when the Gershgorin proof fires
// (sigma_min ~ 250 >> thr = 1e-4 for this data); the fallback overwrites it
// otherwise. Proof: lambda_min(G_full) >= lambda_min(G_subset) >= Gershgorin
// bound on the 4096-column subset Gram (adding columns adds a PSD term).
// ---------------------------------------------------------------------------
__global__ __launch_bounds__(K1_THREADS)
void fused_kernel(const float* __restrict__ x, float* __restrict__ out,
                  const float* __restrict__ soft_thr) {
    int t = threadIdx.x;

    if (blockIdx.x < GRAM_BLOCKS) {
        // ================= subset Gram + inline decide =================
        int g = blockIdx.x;
        int b = g >> 3;
        int chunk = g & 7;
        int k0 = chunk * SUB_CHUNK;

        __shared__ float xs[NC][TILE_K + 1];
        __shared__ int s_ticket;

        int pi0 = 0, pj0 = 0, pi1 = 0, pj1 = 0;
        {
            int tt = t, i = 0;
            while (tt >= NC - i) { tt -= (NC - i); i++; }
            pi0 = i; pj0 = i + tt;
        }
        int t1 = t + K1_THREADS;
        if (t1 < NPAIR) {
            int tt = t1, i = 0;
            while (tt >= NC - i) { tt -= (NC - i); i++; }
            pi1 = i; pj1 = i + tt;
        }

        const float* xb = x + (size_t)b * NC * NHW;
        float acc0 = 0.0f, acc1 = 0.0f;

        for (int kt = 0; kt < SUB_CHUNK; kt += TILE_K) {
            for (int idx = t; idx < NC * TILE_K; idx += K1_THREADS) {
                int c = idx >> 7, kk = idx & (TILE_K - 1);
                xs[c][kk] = xb[c * NHW + k0 + kt + kk];
            }
            __syncthreads();
            #pragma unroll 8
            for (int kk = 0; kk < TILE_K; kk++) {
                acc0 = fmaf(xs[pi0][kk], xs[pj0][kk], acc0);
                acc1 = fmaf(xs[pi1][kk], xs[pj1][kk], acc1);
            }
            __syncthreads();
        }

        g_p1[(b * GRAM_CHUNKS + chunk) * NPAIR + t] = acc0;
        if (t1 < NPAIR)
            g_p1[(b * GRAM_CHUNKS + chunk) * NPAIR + t1] = acc1;

        __threadfence();              // publish partials before ticket
        __syncthreads();
        if (t == 0)
            s_ticket = atomicAdd(&g_cnt[b], 1);
        __syncthreads();
        if (s_ticket == GRAM_CHUNKS - 1) {
            __threadfence();          // acquire other blocks' partials
            if (t < 32) {
                int lane = t;
                float bound = 1e30f;
                if (lane < NC) {
                    float diag = 0.0f, offs = 0.0f;
                    for (int j = 0; j < NC; j++) {
                        int i0 = lane < j ? lane : j;
                        int j0 = lane < j ? j : lane;
                        int tt = pair_index(i0, j0);
                        float gg = 0.0f;
                        #pragma unroll
                        for (int cch = 0; cch < GRAM_CHUNKS; cch++)
                            gg += g_p1[(b * GRAM_CHUNKS + cch) * NPAIR + tt];
                        if (j == lane) diag = gg; else offs += fabsf(gg);
                    }
                    bound = diag - offs;
                }
                for (int o = 16; o > 0; o >>= 1)
                    bound = fminf(bound, __shfl_xor_sync(0xffffffffu, bound, o));
                if (lane == 0) {
                    float thr = soft_thr[0];
                    g_flag[b] = (bound > thr * thr) ? 1 : 0;
                    g_cnt[b] = 0;             // reset for next replay
                    __threadfence();          // release flag before done
                    g_done[b] = 1;
                }
            }
        }
    } else if (blockIdx.x < FB_BASE) {
        // ======================= streaming copy =======================
        // TOTAL4 = 15.5 * span. 7 double-iterations cover spans [0,14);
        // tail loop covers the rest (every i < TOTAL4).
        const float4* src = (const float4*)x;
        float4*       dst = (float4*)out;
        const int span = COPY_BLOCKS * K1_THREADS;   // 524288
        int i = (blockIdx.x - GRAM_BLOCKS) * K1_THREADS + t;
        #pragma unroll 1
        for (int it = 0; it < 7; it++) {
            float4 v0 = __ldcs(src + i);
            float4 v1 = __ldcs(src + i + span);
            __stcs(dst + i, v0);
            __stcs(dst + i + span, v1);
            i += 2 * span;
        }
        #pragma unroll 1
        for (; i < TOTAL4; i += span) {
            float4 v = __ldcs(src + i);
            __stcs(dst + i, v);
        }
    } else {
        // ================= spin + gated fallback (per batch) ==========
        int b = blockIdx.x - FB_BASE;
        __shared__ int s_flag;

        if (t == 0) {
            while (g_done[b] == 0) { /* gram finishes in ~5us */ }
            __threadfence();          // acquire g_flag
            s_flag = g_flag[b];
            g_done[b] = 0;            // reset for next replay
        }
        __syncthreads();
        if (s_flag) return;           // identity proven -> copy stands

        // ---- rare path: full Gram, Jacobi, M = V diag(mask) V^T, M @ x ----
        __shared__ float xs[NC][TILE_K + 1];
        __shared__ float A[NC][NC + 2];
        __shared__ float V[NC][NC + 2];
        __shared__ float M[NC][NC + 1];
        __shared__ float mask[NC];

        const float* xb = x + (size_t)b * NC * NHW;

        int pi0 = 0, pj0 = 0, pi1 = 0, pj1 = 0;
        {
            int tt = t, i = 0;
            while (tt >= NC - i) { tt -= (NC - i); i++; }
            pi0 = i; pj0 = i + tt;
        }
        int t1 = t + K1_THREADS;
        if (t1 < NPAIR) {
            int tt = t1, i = 0;
            while (tt >= NC - i) { tt -= (NC - i); i++; }
            pi1 = i; pj1 = i + tt;
        }

        float acc0 = 0.0f, acc1 = 0.0f;
        for (int k0 = 0; k0 < NHW; k0 += TILE_K) {
            for (int idx = t; idx < NC * TILE_K; idx += K1_THREADS) {
                int c = idx >> 7, kk = idx & (TILE_K - 1);
                xs[c][kk] = xb[c * NHW + k0 + kk];
            }
            __syncthreads();
            #pragma unroll 8
            for (int kk = 0; kk < TILE_K; kk++) {
                acc0 = fmaf(xs[pi0][kk], xs[pj0][kk], acc0);
                acc1 = fmaf(xs[pi1][kk], xs[pj1][kk], acc1);
            }
            __syncthreads();
        }
        A[pi0][pj0] = acc0; A[pj0][pi0] = acc0;
        if (t1 < NPAIR) { A[pi1][pj1] = acc1; A[pj1][pi1] = acc1; }
        for (int idx = t; idx < NC * NC; idx += K1_THREADS) {
            int i = idx / NC, j = idx % NC;
            V[i][j] = (i == j) ? 1.0f : 0.0f;
        }
        __syncthreads();

        if (t < 32) {
            int lane = t;
            for (int sweep = 0; sweep < 12; sweep++) {
                for (int p = 0; p < NC - 1; p++) {
                    for (int q = p + 1; q < NC; q++) {
                        float apq = A[p][q];
                        float app = A[p][p], aqq = A[q][q];
                        if (fabsf(apq) <= 1e-12f * (fabsf(app) + fabsf(aqq)) + 1e-30f)
                            continue;
                        float theta = 0.5f * (aqq - app) / apq;
                        float tt2 = copysignf(1.0f, theta) /
                                    (fabsf(theta) + sqrtf(1.0f + theta * theta));
                        float c = rsqrtf(1.0f + tt2 * tt2);
                        float s = tt2 * c;
                        if (lane < NC) {
                            float Apk = A[p][lane], Aqk = A[q][lane];
                            A[p][lane] = c * Apk - s * Aqk;
                            A[q][lane] = s * Apk + c * Aqk;
                        }
                        __syncwarp();
                        if (lane < NC) {
                            float Akp = A[lane][p], Akq = A[lane][q];
                            A[lane][p] = c * Akp - s * Akq;
                            A[lane][q] = s * Akp + c * Akq;
                            float Vkp = V[lane][p], Vkq = V[lane][q];
                            V[lane][p] = c * Vkp - s * Vkq;
                            V[lane][q] = s * Vkp + c * Vkq;
                        }
                        __syncwarp();
                    }
                }
            }
            if (lane < NC) {
                float sv = sqrtf(fmaxf(A[lane][lane], 0.0f));
                mask[lane] = (sv > soft_thr[0]) ? 1.0f : 0.0f;
            }
            __syncwarp();
            if (lane < NC) {
                for (int r = 0; r < NC; r++) {
                    float m = 0.0f;
                    for (int i = 0; i < NC; i++)
                        m += mask[i] * V[r][i] * V[lane][i];
                    M[r][lane] = m;
                }
            }
        }
        __syncthreads();

        float* ob = out + (size_t)b * NC * NHW;
        for (int k = t; k < NHW; k += K1_THREADS) {
            float xv[NC];
            #pragma unroll
            for (int j = 0; j < NC; j++) xv[j] = xb[(size_t)j * NHW + k];
            #pragma unroll 1
            for (int c = 0; c < NC; c++) {
                float a = 0.0f;
                #pragma unroll
                for (int j = 0; j < NC; j++) a = fmaf(M[c][j], xv[j], a);
                ob[(size_t)c * NHW + k] = a;
            }
        }
    }
}

extern "C" void kernel_launch(void* const* d_in, const int* in_sizes, int n_in,
                              void* d_out, int out_size) {
    // Identify inputs by size (soft_thr has 1 element)
    const float* x   = (const float*)d_in[0];
    const float* thr = (const float*)d_in[1];
    if (n_in >= 2) {
        if (in_sizes[0] == 1) { thr = (const float*)d_in[0]; x = (const float*)d_in[1]; }
        else                  { x  = (const float*)d_in[0]; thr = (const float*)d_in[1]; }
    }
    float* out = (float*)d_out;

    // One fused launch: speculative copy + subset-Gram + decide + gated fallback
    fused_kernel<<<K1_BLOCKS, K1_THREADS>>>(x, out, thr);
}